// round 7
// baseline (speedup 1.0000x reference)
#include <cuda_runtime.h>
#include <cuda_fp16.h>
#include <cstdint>

#define N_NODES 32768
#define EMBED_DIM 512
#define NNZ 1048576
#define LN_EPS 1e-5f

// ---------------- scratch (device globals; no allocation allowed) ----------------
__device__ __align__(16) __half g_support_h[N_NODES * EMBED_DIM];  // 32 MB fp16 support
__device__ int   g_cnt[N_NODES];          // zero-initialized at load; re-zeroed by scan each run
__device__ int   g_ptr[N_NODES + 1];
__device__ int   g_offs[N_NODES];
__device__ __align__(8) int2 g_edge[NNZ]; // (col, val bits)
__device__ __align__(16) __half g_Bt_h[EMBED_DIM * EMBED_DIM];     // W^T fp16, [n][k]

__device__ __forceinline__ uint32_t smem_u32(const void* p) {
    uint32_t a;
    asm("{ .reg .u64 t; cvta.to.shared.u64 t, %1; cvt.u32.u64 %0, t; }" : "=r"(a) : "l"(p));
    return a;
}

// ---------------- prep: W transpose-convert + histogram ----------------
__global__ __launch_bounds__(512) void prep_kernel(const float* __restrict__ W,
                                                   const int* __restrict__ arow) {
    int b = blockIdx.x, t = threadIdx.x;
    if (b < 512) {
        float w = W[b * EMBED_DIM + t];
        g_Bt_h[(size_t)t * EMBED_DIM + b] = __float2half_rn(w);
    } else {
        int e = (b - 512) * 512 + t;
        atomicAdd(&g_cnt[arow[e]], 1);
    }
}

// ---------------- single-block exclusive scan; zeroes g_cnt for next run ----------------
__global__ void scan_kernel() {
    __shared__ int sh[1024];
    int t = threadIdx.x;
    int base = t * 32;
    int local[32];
    int sum = 0;
#pragma unroll
    for (int j = 0; j < 32; j++) {
        local[j] = g_cnt[base + j];
        g_cnt[base + j] = 0;      // reset for next graph replay
        sum += local[j];
    }
    sh[t] = sum;
    __syncthreads();
    for (int o = 1; o < 1024; o <<= 1) {
        int v = (t >= o) ? sh[t - o] : 0;
        __syncthreads();
        sh[t] += v;
        __syncthreads();
    }
    int run = sh[t] - sum;
#pragma unroll
    for (int j = 0; j < 32; j++) {
        g_ptr[base + j] = run;
        g_offs[base + j] = run;
        run += local[j];
    }
    if (t == 1023) g_ptr[N_NODES] = run;
}

// ---------------- GEMM (uid-gathered fp32 A via cp.async, fp16 B) + edge scatter ----------------
// GEMM blocks [0,1024): CTA tile 128(M)x128(N); 16 k-chunks of 32 (floats/halves).
// Stage: A32 16KB + B16 8KB = 24KB; 3 stages = 72KB dynamic smem.
// Scatter blocks [1024,5120).
#define STAGE_SZ 24576
#define N_CHUNKS 16

__device__ __forceinline__ uint32_t sw_off(int row, int un) {   // B tile: 64B rows
    return (uint32_t)(row * 64 + ((un ^ ((row >> 1) & 3)) << 4));
}

__global__ __launch_bounds__(256, 2) void gemm_scatter(const int* __restrict__ uid,
                                                       const float* __restrict__ emb,
                                                       const int* __restrict__ arow,
                                                       const int* __restrict__ acol,
                                                       const float* __restrict__ avals) {
    extern __shared__ char dyn[];
    int tid = threadIdx.x;

    if (blockIdx.x >= 1024) {
        int e = (blockIdx.x - 1024) * 256 + tid;
        int r = arow[e];
        int p = atomicAdd(&g_offs[r], 1);
        g_edge[p] = make_int2(acol[e], __float_as_int(avals[e]));
        return;
    }

    __shared__ int s_uid[128];
    int lane = tid & 31, wid = tid >> 5;
    int warp_m = wid & 3, warp_n = wid >> 2;
    int m0 = (blockIdx.x >> 2) * 128, n0 = (blockIdx.x & 3) * 128;

    if (tid < 128) s_uid[tid] = uid[m0 + tid];
    __syncthreads();

    // Per-thread A gather setup: 4 segs per stage. seg s = tid + j*256 -> row s>>3, unit s&7.
    const char* asrc[4];
    uint32_t aswz[4];
    {
        int u = tid & 7;
#pragma unroll
        for (int j = 0; j < 4; j++) {
            int r = (tid >> 3) + j * 32;
            asrc[j] = (const char*)(emb + (size_t)s_uid[r] * EMBED_DIM) + u * 16;
            aswz[j] = (uint32_t)(r * 128 + ((u ^ (r & 7)) << 4));
        }
    }
    const char* Bg = (const char*)g_Bt_h + (size_t)n0 * 1024;

    uint32_t sbase = (smem_u32(dyn) + 127u) & ~127u;

    float acc[2][8][4];
#pragma unroll
    for (int mt = 0; mt < 2; mt++)
#pragma unroll
        for (int nt = 0; nt < 8; nt++)
#pragma unroll
            for (int q = 0; q < 4; q++) acc[mt][nt][q] = 0.f;

    // stage loader: A fp32 (uid gather) + B fp16
    auto ld_stage = [&](int stage, int chunk) {
        uint32_t st = sbase + stage * STAGE_SZ;
        size_t aoff = (size_t)chunk * 128;   // 32 floats
#pragma unroll
        for (int j = 0; j < 4; j++) {
            asm volatile("cp.async.cg.shared.global [%0], [%1], 16;"
                         :: "r"(st + aswz[j]), "l"(asrc[j] + aoff));
        }
        uint32_t bs = st + 16384;
        size_t boff = (size_t)chunk * 64;    // 32 halves
#pragma unroll
        for (int j = 0; j < 2; j++) {
            int u = tid + j * 256;
            int row = u >> 2, un = u & 3;
            asm volatile("cp.async.cg.shared.global [%0], [%1], 16;"
                         :: "r"(bs + sw_off(row, un)),
                            "l"(Bg + (size_t)row * 1024 + boff + un * 16));
        }
    };

    ld_stage(0, 0);
    asm volatile("cp.async.commit_group;");
    ld_stage(1, 1);
    asm volatile("cp.async.commit_group;");

    for (int i = 0; i < N_CHUNKS; i++) {
        if (i < N_CHUNKS - 1) {
            asm volatile("cp.async.wait_group 1;");
        } else {
            asm volatile("cp.async.wait_group 0;");
        }
        __syncthreads();
        if (i + 2 < N_CHUNKS) {
            ld_stage((i + 2) % 3, i + 2);
            asm volatile("cp.async.commit_group;");
        }

        uint32_t aB = sbase + (i % 3) * STAGE_SZ;
        uint32_t bB = aB + 16384;
#pragma unroll
        for (int kk = 0; kk < 2; kk++) {
            uint32_t b[8][2];
#pragma unroll
            for (int p = 0; p < 4; p++) {
                int row = warp_n * 64 + p * 16 + (lane >> 4) * 8 + (lane & 7);
                int un = kk * 2 + ((lane >> 3) & 1);
                uint32_t addr = bB + sw_off(row, un);
                asm volatile("ldmatrix.sync.aligned.m8n8.x4.shared.b16 {%0,%1,%2,%3}, [%4];"
                             : "=r"(b[2 * p][0]), "=r"(b[2 * p][1]),
                               "=r"(b[2 * p + 1][0]), "=r"(b[2 * p + 1][1])
                             : "r"(addr));
            }
#pragma unroll
            for (int mt = 0; mt < 2; mt++) {
                // A fragment from fp32 smem: rows r, r+8; float cols kb, kb+8
                int r = warp_m * 32 + mt * 16 + (lane >> 2);
                int kb = kk * 16 + (lane & 3) * 2;
                uint32_t a[4];
#pragma unroll
                for (int q = 0; q < 4; q++) {
                    int rr = r + (q & 1) * 8;
                    int kc = kb + (q >> 1) * 8;
                    uint32_t addr = aB + (uint32_t)(rr * 128) +
                                    ((((uint32_t)kc >> 2) ^ (uint32_t)(rr & 7)) << 4) +
                                    ((kc & 3) * 4);
                    float x, y;
                    asm volatile("ld.shared.v2.f32 {%0,%1}, [%2];"
                                 : "=f"(x), "=f"(y) : "r"(addr));
                    __half2 h = __floats2half2_rn(x, y);
                    a[q] = *(uint32_t*)&h;
                }
#pragma unroll
                for (int nt = 0; nt < 8; nt++) {
                    asm volatile(
                        "mma.sync.aligned.m16n8k16.row.col.f32.f16.f16.f32 "
                        "{%0,%1,%2,%3}, {%4,%5,%6,%7}, {%8,%9}, {%0,%1,%2,%3};"
                        : "+f"(acc[mt][nt][0]), "+f"(acc[mt][nt][1]),
                          "+f"(acc[mt][nt][2]), "+f"(acc[mt][nt][3])
                        : "r"(a[0]), "r"(a[1]), "r"(a[2]), "r"(a[3]),
                          "r"(b[nt][0]), "r"(b[nt][1]));
                }
            }
        }
        __syncthreads();
    }

    // epilogue: fp16 support store
    int g = lane >> 2, tg = lane & 3;
#pragma unroll
    for (int mt = 0; mt < 2; mt++) {
        int m = m0 + warp_m * 32 + mt * 16 + g;
#pragma unroll
        for (int nt = 0; nt < 8; nt++) {
            int n = n0 + warp_n * 64 + nt * 8 + tg * 2;
            __half2 lo2 = __floats2half2_rn(acc[mt][nt][0], acc[mt][nt][1]);
            __half2 hi2 = __floats2half2_rn(acc[mt][nt][2], acc[mt][nt][3]);
            *(__half2*)(g_support_h + (size_t)m * EMBED_DIM + n) = lo2;
            *(__half2*)(g_support_h + (size_t)(m + 8) * EMBED_DIM + n) = hi2;
        }
    }
}

// ---------------- fused SpMM (CSR, fp16 support) + bias + LayerNorm ----------------
// 64 threads per row; thread owns 8 dims (one 16B load per edge).
__global__ __launch_bounds__(64) void spmm_ln_kernel(const float* __restrict__ bias,
                                                     const float* __restrict__ gamma,
                                                     const float* __restrict__ beta,
                                                     float* __restrict__ out) {
    int r = blockIdx.x;
    int t = threadIdx.x;
    __shared__ int2 s_edge[64];
    __shared__ float red[4];

    int beg = g_ptr[r];
    int end = g_ptr[r + 1];

    float acc[8];
#pragma unroll
    for (int q = 0; q < 8; q++) acc[q] = 0.f;

    for (int base = beg; base < end; base += 64) {
        int cnt = min(64, end - base);
        if (t < cnt) s_edge[t] = g_edge[base + t];
        __syncthreads();
#pragma unroll 4
        for (int i = 0; i < cnt; i++) {
            int2 e = s_edge[i];
            float v = __int_as_float(e.y);
            uint4 raw = *(const uint4*)(g_support_h + (size_t)e.x * EMBED_DIM + t * 8);
            float2 f0 = __half22float2(*reinterpret_cast<__half2*>(&raw.x));
            float2 f1 = __half22float2(*reinterpret_cast<__half2*>(&raw.y));
            float2 f2 = __half22float2(*reinterpret_cast<__half2*>(&raw.z));
            float2 f3 = __half22float2(*reinterpret_cast<__half2*>(&raw.w));
            acc[0] += v * f0.x; acc[1] += v * f0.y;
            acc[2] += v * f1.x; acc[3] += v * f1.y;
            acc[4] += v * f2.x; acc[5] += v * f2.y;
            acc[6] += v * f3.x; acc[7] += v * f3.y;
        }
        __syncthreads();
    }

    const float4* b4 = (const float4*)(bias + t * 8);
    float4 ba = b4[0], bb = b4[1];
    acc[0] += ba.x; acc[1] += ba.y; acc[2] += ba.z; acc[3] += ba.w;
    acc[4] += bb.x; acc[5] += bb.y; acc[6] += bb.z; acc[7] += bb.w;

    float s = 0.f, q = 0.f;
#pragma unroll
    for (int j = 0; j < 8; j++) { s += acc[j]; q += acc[j] * acc[j]; }
#pragma unroll
    for (int o = 16; o > 0; o >>= 1) {
        s += __shfl_down_sync(0xFFFFFFFFu, s, o);
        q += __shfl_down_sync(0xFFFFFFFFu, q, o);
    }
    int lane = t & 31, w = t >> 5;
    if (lane == 0) { red[w] = s; red[2 + w] = q; }
    __syncthreads();
    if (t == 0) {
        float S = red[0] + red[1];
        float Q = red[2] + red[3];
        float mu = S * (1.0f / EMBED_DIM);
        float var = Q * (1.0f / EMBED_DIM) - mu * mu;
        red[0] = mu;
        red[1] = rsqrtf(var + LN_EPS);
    }
    __syncthreads();
    float mu = red[0], rs = red[1];

    const float4* g4 = (const float4*)(gamma + t * 8);
    const float4* be4 = (const float4*)(beta + t * 8);
    float4 g0 = g4[0], g1 = g4[1], e0 = be4[0], e1 = be4[1];
    float4 o0, o1;
    o0.x = (acc[0] - mu) * rs * g0.x + e0.x;
    o0.y = (acc[1] - mu) * rs * g0.y + e0.y;
    o0.z = (acc[2] - mu) * rs * g0.z + e0.z;
    o0.w = (acc[3] - mu) * rs * g0.w + e0.w;
    o1.x = (acc[4] - mu) * rs * g1.x + e1.x;
    o1.y = (acc[5] - mu) * rs * g1.y + e1.y;
    o1.z = (acc[6] - mu) * rs * g1.z + e1.z;
    o1.w = (acc[7] - mu) * rs * g1.w + e1.w;
    float4* op = (float4*)(out + (size_t)r * EMBED_DIM + t * 8);
    op[0] = o0;
    op[1] = o1;
}

// ---------------- launch ----------------
extern "C" void kernel_launch(void* const* d_in, const int* in_sizes, int n_in,
                              void* d_out, int out_size) {
    const int*   uid   = (const int*)d_in[0];
    const int*   arow  = (const int*)d_in[1];
    const int*   acol  = (const int*)d_in[2];
    const float* avals = (const float*)d_in[3];
    const float* emb   = (const float*)d_in[4];
    const float* W     = (const float*)d_in[5];
    const float* bias  = (const float*)d_in[6];
    const float* gamma = (const float*)d_in[7];
    const float* beta  = (const float*)d_in[8];
    float* out = (float*)d_out;

    static bool attr = false;
    if (!attr) {
        cudaFuncSetAttribute(gemm_scatter, cudaFuncAttributeMaxDynamicSharedMemorySize,
                             3 * STAGE_SZ + 128);
        attr = true;
    }

    prep_kernel<<<2560, 512>>>(W, arow);
    scan_kernel<<<1, 1024>>>();
    gemm_scatter<<<5120, 256, 3 * STAGE_SZ + 128>>>(uid, emb, arow, acol, avals);
    spmm_ln_kernel<<<N_NODES, 64>>>(bias, gamma, beta, out);
}

// round 8
// speedup vs baseline: 1.0175x; 1.0175x over previous
#include <cuda_runtime.h>
#include <cuda_fp16.h>
#include <cstdint>

#define N_NODES 32768
#define EMBED_DIM 512
#define NNZ 1048576
#define LN_EPS 1e-5f

// ---------------- scratch (device globals; no allocation allowed) ----------------
__device__ __align__(16) __half g_support_h[N_NODES * EMBED_DIM];  // 32 MB fp16 support
__device__ int   g_cnt[N_NODES];          // zero-initialized at load; re-zeroed by scan each run
__device__ int   g_ptr[N_NODES + 1];
__device__ int   g_offs[N_NODES];
__device__ __align__(8) int2 g_edge[NNZ]; // (col, val bits)
__device__ __align__(16) __half g_A_h[N_NODES * EMBED_DIM];        // 32 MB fp16 gathered A
__device__ __align__(16) __half g_Bt_h[EMBED_DIM * EMBED_DIM];     // W^T fp16, [n][k]

__device__ __forceinline__ uint32_t smem_u32(const void* p) {
    uint32_t a;
    asm("{ .reg .u64 t; cvta.to.shared.u64 t, %1; cvt.u32.u64 %0, t; }" : "=r"(a) : "l"(p));
    return a;
}

// ---------------- prep: W transpose-convert + histogram ----------------
__global__ __launch_bounds__(512) void prep_kernel(const float* __restrict__ W,
                                                   const int* __restrict__ arow) {
    int b = blockIdx.x, t = threadIdx.x;
    if (b < 512) {
        float w = W[b * EMBED_DIM + t];
        g_Bt_h[(size_t)t * EMBED_DIM + b] = __float2half_rn(w);
    } else {
        int e = (b - 512) * 512 + t;
        atomicAdd(&g_cnt[arow[e]], 1);
    }
}

// ---------------- gather: embedding rows -> fp16 A ----------------
__global__ __launch_bounds__(256) void gather_kernel(const int* __restrict__ uid,
                                                     const float* __restrict__ emb) {
    int b = blockIdx.x, t = threadIdx.x;
    int row = b * 4 + (t >> 6);
    int c = (t & 63) * 8;
    int u = __ldg(uid + row);
    const float4* src = (const float4*)(emb + (size_t)u * EMBED_DIM + c);
    float4 v0 = src[0];
    float4 v1 = src[1];
    __half2 h0 = __floats2half2_rn(v0.x, v0.y);
    __half2 h1 = __floats2half2_rn(v0.z, v0.w);
    __half2 h2 = __floats2half2_rn(v1.x, v1.y);
    __half2 h3 = __floats2half2_rn(v1.z, v1.w);
    uint4* dst = (uint4*)(g_A_h + (size_t)row * EMBED_DIM + c);
    dst[0] = make_uint4(*(uint32_t*)&h0, *(uint32_t*)&h1, *(uint32_t*)&h2, *(uint32_t*)&h3);
}

// ---------------- single-block exclusive scan; zeroes g_cnt for next run ----------------
__global__ void scan_kernel() {
    __shared__ int sh[1024];
    int t = threadIdx.x;
    int base = t * 32;
    int local[32];
    int sum = 0;
#pragma unroll
    for (int j = 0; j < 32; j++) {
        local[j] = g_cnt[base + j];
        g_cnt[base + j] = 0;      // reset for next graph replay
        sum += local[j];
    }
    sh[t] = sum;
    __syncthreads();
    for (int o = 1; o < 1024; o <<= 1) {
        int v = (t >= o) ? sh[t - o] : 0;
        __syncthreads();
        sh[t] += v;
        __syncthreads();
    }
    int run = sh[t] - sum;
#pragma unroll
    for (int j = 0; j < 32; j++) {
        g_ptr[base + j] = run;
        g_offs[base + j] = run;
        run += local[j];
    }
    if (t == 1023) g_ptr[N_NODES] = run;
}

// ---------------- GEMM (single-pass fp16, materialized A) fused with edge scatter ----------------
// GEMM blocks [0,1024): CTA tile 128(M)x128(N), 16 k-chunks of 32 halves.
// Stage: A 8KB + B 8KB = 16KB; 3 stages (48KB static smem).
// Scatter blocks [1024,5120).
#define STAGE_B 16384
#define N_CHUNKS 16

__device__ __forceinline__ uint32_t sw_off(int row, int un) {
    return (uint32_t)(row * 64 + ((un ^ ((row >> 1) & 3)) << 4));
}

__device__ __forceinline__ void ld_stage(uint32_t st, const char* Ag, const char* Bg, int tid) {
#pragma unroll
    for (int j = 0; j < 2; j++) {
        int u = tid + j * 256;
        int row = u >> 2, un = u & 3;
        uint32_t so = sw_off(row, un);
        size_t go = (size_t)row * 1024 + un * 16;
        asm volatile("cp.async.cg.shared.global [%0], [%1], 16;" :: "r"(st + so), "l"(Ag + go));
        asm volatile("cp.async.cg.shared.global [%0], [%1], 16;" :: "r"(st + 8192 + so), "l"(Bg + go));
    }
}

__global__ __launch_bounds__(256, 2) void gemm_scatter(const int* __restrict__ arow,
                                                       const int* __restrict__ acol,
                                                       const float* __restrict__ avals) {
    __shared__ __align__(128) char smem[3 * STAGE_B];
    int tid = threadIdx.x;

    if (blockIdx.x >= 1024) {
        int e = (blockIdx.x - 1024) * 256 + tid;
        int r = arow[e];
        int p = atomicAdd(&g_offs[r], 1);
        g_edge[p] = make_int2(acol[e], __float_as_int(avals[e]));
        return;
    }

    int lane = tid & 31, wid = tid >> 5;
    int warp_m = wid & 3, warp_n = wid >> 2;
    int m0 = (blockIdx.x >> 2) * 128, n0 = (blockIdx.x & 3) * 128;

    float acc[2][8][4];
#pragma unroll
    for (int mt = 0; mt < 2; mt++)
#pragma unroll
        for (int nt = 0; nt < 8; nt++)
#pragma unroll
            for (int q = 0; q < 4; q++) acc[mt][nt][q] = 0.f;

    const char* Ag = (const char*)g_A_h + (size_t)m0 * 1024;
    const char* Bg = (const char*)g_Bt_h + (size_t)n0 * 1024;

    uint32_t sbase = smem_u32(smem);

    ld_stage(sbase, Ag, Bg, tid);
    asm volatile("cp.async.commit_group;");
    ld_stage(sbase + STAGE_B, Ag + 64, Bg + 64, tid);
    asm volatile("cp.async.commit_group;");

    for (int i = 0; i < N_CHUNKS; i++) {
        if (i < N_CHUNKS - 1) {
            asm volatile("cp.async.wait_group 1;");
        } else {
            asm volatile("cp.async.wait_group 0;");
        }
        __syncthreads();
        if (i + 2 < N_CHUNKS) {
            int koff = (i + 2) * 64;
            ld_stage(sbase + ((i + 2) % 3) * STAGE_B, Ag + koff, Bg + koff, tid);
            asm volatile("cp.async.commit_group;");
        }

        uint32_t aB = sbase + (i % 3) * STAGE_B;
        uint32_t bB = aB + 8192;
#pragma unroll
        for (int kk = 0; kk < 2; kk++) {
            uint32_t b[8][2];
#pragma unroll
            for (int p = 0; p < 4; p++) {
                int row = warp_n * 64 + p * 16 + (lane >> 4) * 8 + (lane & 7);
                int un = kk * 2 + ((lane >> 3) & 1);
                uint32_t addr = bB + sw_off(row, un);
                asm volatile("ldmatrix.sync.aligned.m8n8.x4.shared.b16 {%0,%1,%2,%3}, [%4];"
                             : "=r"(b[2 * p][0]), "=r"(b[2 * p][1]),
                               "=r"(b[2 * p + 1][0]), "=r"(b[2 * p + 1][1])
                             : "r"(addr));
            }
            uint32_t a[2][4];
#pragma unroll
            for (int mt = 0; mt < 2; mt++) {
                int row = warp_m * 32 + mt * 16 + ((lane >> 3) & 1) * 8 + (lane & 7);
                int un = kk * 2 + (lane >> 4);
                uint32_t addr = aB + sw_off(row, un);
                asm volatile("ldmatrix.sync.aligned.m8n8.x4.shared.b16 {%0,%1,%2,%3}, [%4];"
                             : "=r"(a[mt][0]), "=r"(a[mt][1]), "=r"(a[mt][2]), "=r"(a[mt][3])
                             : "r"(addr));
            }
#pragma unroll
            for (int mt = 0; mt < 2; mt++)
#pragma unroll
                for (int nt = 0; nt < 8; nt++) {
                    asm volatile(
                        "mma.sync.aligned.m16n8k16.row.col.f32.f16.f16.f32 "
                        "{%0,%1,%2,%3}, {%4,%5,%6,%7}, {%8,%9}, {%0,%1,%2,%3};"
                        : "+f"(acc[mt][nt][0]), "+f"(acc[mt][nt][1]),
                          "+f"(acc[mt][nt][2]), "+f"(acc[mt][nt][3])
                        : "r"(a[mt][0]), "r"(a[mt][1]), "r"(a[mt][2]), "r"(a[mt][3]),
                          "r"(b[nt][0]), "r"(b[nt][1]));
                }
        }
        __syncthreads();
    }

    // epilogue: fp16 support store
    int g = lane >> 2, tg = lane & 3;
#pragma unroll
    for (int mt = 0; mt < 2; mt++) {
        int m = m0 + warp_m * 32 + mt * 16 + g;
#pragma unroll
        for (int nt = 0; nt < 8; nt++) {
            int n = n0 + warp_n * 64 + nt * 8 + tg * 2;
            __half2 lo2 = __floats2half2_rn(acc[mt][nt][0], acc[mt][nt][1]);
            __half2 hi2 = __floats2half2_rn(acc[mt][nt][2], acc[mt][nt][3]);
            *(__half2*)(g_support_h + (size_t)m * EMBED_DIM + n) = lo2;
            *(__half2*)(g_support_h + (size_t)(m + 8) * EMBED_DIM + n) = hi2;
        }
    }
}

// ---------------- fused SpMM (CSR, fp16 support) + bias + LayerNorm ----------------
// 64 threads per row; thread owns 8 dims (one 16B load per edge).
__global__ __launch_bounds__(64) void spmm_ln_kernel(const float* __restrict__ bias,
                                                     const float* __restrict__ gamma,
                                                     const float* __restrict__ beta,
                                                     float* __restrict__ out) {
    int r = blockIdx.x;
    int t = threadIdx.x;
    __shared__ int2 s_edge[64];
    __shared__ float red[4];

    int beg = g_ptr[r];
    int end = g_ptr[r + 1];

    float acc[8];
#pragma unroll
    for (int q = 0; q < 8; q++) acc[q] = 0.f;

    for (int base = beg; base < end; base += 64) {
        int cnt = min(64, end - base);
        if (t < cnt) s_edge[t] = g_edge[base + t];
        __syncthreads();
#pragma unroll 4
        for (int i = 0; i < cnt; i++) {
            int2 e = s_edge[i];
            float v = __int_as_float(e.y);
            uint4 raw = *(const uint4*)(g_support_h + (size_t)e.x * EMBED_DIM + t * 8);
            float2 f0 = __half22float2(*reinterpret_cast<__half2*>(&raw.x));
            float2 f1 = __half22float2(*reinterpret_cast<__half2*>(&raw.y));
            float2 f2 = __half22float2(*reinterpret_cast<__half2*>(&raw.z));
            float2 f3 = __half22float2(*reinterpret_cast<__half2*>(&raw.w));
            acc[0] += v * f0.x; acc[1] += v * f0.y;
            acc[2] += v * f1.x; acc[3] += v * f1.y;
            acc[4] += v * f2.x; acc[5] += v * f2.y;
            acc[6] += v * f3.x; acc[7] += v * f3.y;
        }
        __syncthreads();
    }

    const float4* b4 = (const float4*)(bias + t * 8);
    float4 ba = b4[0], bb = b4[1];
    acc[0] += ba.x; acc[1] += ba.y; acc[2] += ba.z; acc[3] += ba.w;
    acc[4] += bb.x; acc[5] += bb.y; acc[6] += bb.z; acc[7] += bb.w;

    float s = 0.f, q = 0.f;
#pragma unroll
    for (int j = 0; j < 8; j++) { s += acc[j]; q += acc[j] * acc[j]; }
#pragma unroll
    for (int o = 16; o > 0; o >>= 1) {
        s += __shfl_down_sync(0xFFFFFFFFu, s, o);
        q += __shfl_down_sync(0xFFFFFFFFu, q, o);
    }
    int lane = t & 31, w = t >> 5;
    if (lane == 0) { red[w] = s; red[2 + w] = q; }
    __syncthreads();
    if (t == 0) {
        float S = red[0] + red[1];
        float Q = red[2] + red[3];
        float mu = S * (1.0f / EMBED_DIM);
        float var = Q * (1.0f / EMBED_DIM) - mu * mu;
        red[0] = mu;
        red[1] = rsqrtf(var + LN_EPS);
    }
    __syncthreads();
    float mu = red[0], rs = red[1];

    const float4* g4 = (const float4*)(gamma + t * 8);
    const float4* be4 = (const float4*)(beta + t * 8);
    float4 g0 = g4[0], g1 = g4[1], e0 = be4[0], e1 = be4[1];
    float4 o0, o1;
    o0.x = (acc[0] - mu) * rs * g0.x + e0.x;
    o0.y = (acc[1] - mu) * rs * g0.y + e0.y;
    o0.z = (acc[2] - mu) * rs * g0.z + e0.z;
    o0.w = (acc[3] - mu) * rs * g0.w + e0.w;
    o1.x = (acc[4] - mu) * rs * g1.x + e1.x;
    o1.y = (acc[5] - mu) * rs * g1.y + e1.y;
    o1.z = (acc[6] - mu) * rs * g1.z + e1.z;
    o1.w = (acc[7] - mu) * rs * g1.w + e1.w;
    float4* op = (float4*)(out + (size_t)r * EMBED_DIM + t * 8);
    op[0] = o0;
    op[1] = o1;
}

// ---------------- launch ----------------
extern "C" void kernel_launch(void* const* d_in, const int* in_sizes, int n_in,
                              void* d_out, int out_size) {
    const int*   uid   = (const int*)d_in[0];
    const int*   arow  = (const int*)d_in[1];
    const int*   acol  = (const int*)d_in[2];
    const float* avals = (const float*)d_in[3];
    const float* emb   = (const float*)d_in[4];
    const float* W     = (const float*)d_in[5];
    const float* bias  = (const float*)d_in[6];
    const float* gamma = (const float*)d_in[7];
    const float* beta  = (const float*)d_in[8];
    float* out = (float*)d_out;

    prep_kernel<<<2560, 512>>>(W, arow);
    gather_kernel<<<8192, 256>>>(uid, emb);
    scan_kernel<<<1, 1024>>>();
    gemm_scatter<<<5120, 256>>>(arow, acol, avals);
    spmm_ln_kernel<<<N_NODES, 64>>>(bias, gamma, beta, out);
}

// round 9
// speedup vs baseline: 1.3900x; 1.3662x over previous
#include <cuda_runtime.h>
#include <cuda_fp16.h>
#include <cstdint>

#define N_NODES 32768
#define EMBED_DIM 512
#define NNZ 1048576
#define LN_EPS 1e-5f

// ---------------- scratch (device globals; no allocation allowed) ----------------
__device__ __align__(16) __half g_support_h[N_NODES * EMBED_DIM];  // 32 MB fp16 support
__device__ int   g_cnt[N_NODES];          // zero-init at load; re-zeroed by scanA each run
__device__ int   g_ptr[N_NODES + 1];
__device__ int   g_offs[N_NODES];
__device__ int   g_bsum[32];
__device__ __align__(8) int2 g_edge[NNZ]; // (col, val bits)
__device__ __align__(16) __half g_A_h[N_NODES * EMBED_DIM];        // 32 MB fp16 gathered A
__device__ __align__(16) __half g_Bt_h[EMBED_DIM * EMBED_DIM];     // W^T fp16, [n][k]

__device__ __forceinline__ uint32_t smem_u32(const void* p) {
    uint32_t a;
    asm("{ .reg .u64 t; cvta.to.shared.u64 t, %1; cvt.u32.u64 %0, t; }" : "=r"(a) : "l"(p));
    return a;
}

// ---------------- prep_all: W transpose + edge histogram + embedding gather ----------------
// blocks [0,1024): W transpose; [1024,5120): hist; [5120,13312): gather.
__global__ __launch_bounds__(256) void prep_all(const float* __restrict__ W,
                                                const int* __restrict__ arow,
                                                const int* __restrict__ uid,
                                                const float* __restrict__ emb) {
    int b = blockIdx.x, t = threadIdx.x;
    if (b < 1024) {
        int k = b >> 1;
        int n = ((b & 1) << 8) + t;
        g_Bt_h[(size_t)n * EMBED_DIM + k] = __float2half_rn(W[k * EMBED_DIM + n]);
    } else if (b < 5120) {
        int e = (b - 1024) * 256 + t;
        atomicAdd(&g_cnt[arow[e]], 1);
    } else {
        int row = (b - 5120) * 4 + (t >> 6);
        int c = (t & 63) * 8;
        int u = __ldg(uid + row);
        const float4* src = (const float4*)(emb + (size_t)u * EMBED_DIM + c);
        float4 v0 = src[0];
        float4 v1 = src[1];
        __half2 h0 = __floats2half2_rn(v0.x, v0.y);
        __half2 h1 = __floats2half2_rn(v0.z, v0.w);
        __half2 h2 = __floats2half2_rn(v1.x, v1.y);
        __half2 h3 = __floats2half2_rn(v1.z, v1.w);
        uint4* dst = (uint4*)(g_A_h + (size_t)row * EMBED_DIM + c);
        dst[0] = make_uint4(*(uint32_t*)&h0, *(uint32_t*)&h1, *(uint32_t*)&h2, *(uint32_t*)&h3);
    }
}

// ---------------- scan phase A: per-1024-chunk exclusive scan (coalesced) ----------------
__global__ __launch_bounds__(1024) void scanA_kernel() {
    __shared__ int sh[1024];
    int b = blockIdx.x, t = threadIdx.x;
    int idx = b * 1024 + t;
    int v = g_cnt[idx];
    g_cnt[idx] = 0;                      // reset for next graph replay
    sh[t] = v;
    __syncthreads();
    for (int o = 1; o < 1024; o <<= 1) {
        int tmp = (t >= o) ? sh[t - o] : 0;
        __syncthreads();
        sh[t] += tmp;
        __syncthreads();
    }
    g_ptr[idx] = sh[t] - v;              // local exclusive prefix
    if (t == 1023) g_bsum[b] = sh[t];
}

// ---------------- scan phase B: add block offsets, write g_offs ----------------
__global__ __launch_bounds__(1024) void scanB_kernel() {
    __shared__ int boff[33];
    int t = threadIdx.x;
    if (t == 0) {
        int run = 0;
#pragma unroll
        for (int i = 0; i < 32; i++) { boff[i] = run; run += g_bsum[i]; }
        boff[32] = run;
    }
    __syncthreads();
#pragma unroll
    for (int j = 0; j < 32; j++) {
        int idx = j * 1024 + t;
        int val = g_ptr[idx] + boff[j];
        g_ptr[idx] = val;
        g_offs[idx] = val;
    }
    if (t == 0) g_ptr[N_NODES] = boff[32];
}

// ---------------- GEMM (single-pass fp16, materialized A) fused with edge scatter ----------------
#define STAGE_B 16384
#define N_CHUNKS 16

__device__ __forceinline__ uint32_t sw_off(int row, int un) {
    return (uint32_t)(row * 64 + ((un ^ ((row >> 1) & 3)) << 4));
}

__device__ __forceinline__ void ld_stage(uint32_t st, const char* Ag, const char* Bg, int tid) {
#pragma unroll
    for (int j = 0; j < 2; j++) {
        int u = tid + j * 256;
        int row = u >> 2, un = u & 3;
        uint32_t so = sw_off(row, un);
        size_t go = (size_t)row * 1024 + un * 16;
        asm volatile("cp.async.cg.shared.global [%0], [%1], 16;" :: "r"(st + so), "l"(Ag + go));
        asm volatile("cp.async.cg.shared.global [%0], [%1], 16;" :: "r"(st + 8192 + so), "l"(Bg + go));
    }
}

__global__ __launch_bounds__(256, 2) void gemm_scatter(const int* __restrict__ arow,
                                                       const int* __restrict__ acol,
                                                       const float* __restrict__ avals) {
    __shared__ __align__(128) char smem[3 * STAGE_B];
    int tid = threadIdx.x;

    if (blockIdx.x >= 1024) {
        int e = (blockIdx.x - 1024) * 256 + tid;
        int r = arow[e];
        int p = atomicAdd(&g_offs[r], 1);
        g_edge[p] = make_int2(acol[e], __float_as_int(avals[e]));
        return;
    }

    int lane = tid & 31, wid = tid >> 5;
    int warp_m = wid & 3, warp_n = wid >> 2;
    int m0 = (blockIdx.x >> 2) * 128, n0 = (blockIdx.x & 3) * 128;

    float acc[2][8][4];
#pragma unroll
    for (int mt = 0; mt < 2; mt++)
#pragma unroll
        for (int nt = 0; nt < 8; nt++)
#pragma unroll
            for (int q = 0; q < 4; q++) acc[mt][nt][q] = 0.f;

    const char* Ag = (const char*)g_A_h + (size_t)m0 * 1024;
    const char* Bg = (const char*)g_Bt_h + (size_t)n0 * 1024;

    uint32_t sbase = smem_u32(smem);

    ld_stage(sbase, Ag, Bg, tid);
    asm volatile("cp.async.commit_group;");
    ld_stage(sbase + STAGE_B, Ag + 64, Bg + 64, tid);
    asm volatile("cp.async.commit_group;");

    for (int i = 0; i < N_CHUNKS; i++) {
        if (i < N_CHUNKS - 1) {
            asm volatile("cp.async.wait_group 1;");
        } else {
            asm volatile("cp.async.wait_group 0;");
        }
        __syncthreads();
        if (i + 2 < N_CHUNKS) {
            int koff = (i + 2) * 64;
            ld_stage(sbase + ((i + 2) % 3) * STAGE_B, Ag + koff, Bg + koff, tid);
            asm volatile("cp.async.commit_group;");
        }

        uint32_t aB = sbase + (i % 3) * STAGE_B;
        uint32_t bB = aB + 8192;
#pragma unroll
        for (int kk = 0; kk < 2; kk++) {
            uint32_t b[8][2];
#pragma unroll
            for (int p = 0; p < 4; p++) {
                int row = warp_n * 64 + p * 16 + (lane >> 4) * 8 + (lane & 7);
                int un = kk * 2 + ((lane >> 3) & 1);
                uint32_t addr = bB + sw_off(row, un);
                asm volatile("ldmatrix.sync.aligned.m8n8.x4.shared.b16 {%0,%1,%2,%3}, [%4];"
                             : "=r"(b[2 * p][0]), "=r"(b[2 * p][1]),
                               "=r"(b[2 * p + 1][0]), "=r"(b[2 * p + 1][1])
                             : "r"(addr));
            }
            uint32_t a[2][4];
#pragma unroll
            for (int mt = 0; mt < 2; mt++) {
                int row = warp_m * 32 + mt * 16 + ((lane >> 3) & 1) * 8 + (lane & 7);
                int un = kk * 2 + (lane >> 4);
                uint32_t addr = aB + sw_off(row, un);
                asm volatile("ldmatrix.sync.aligned.m8n8.x4.shared.b16 {%0,%1,%2,%3}, [%4];"
                             : "=r"(a[mt][0]), "=r"(a[mt][1]), "=r"(a[mt][2]), "=r"(a[mt][3])
                             : "r"(addr));
            }
#pragma unroll
            for (int mt = 0; mt < 2; mt++)
#pragma unroll
                for (int nt = 0; nt < 8; nt++) {
                    asm volatile(
                        "mma.sync.aligned.m16n8k16.row.col.f32.f16.f16.f32 "
                        "{%0,%1,%2,%3}, {%4,%5,%6,%7}, {%8,%9}, {%0,%1,%2,%3};"
                        : "+f"(acc[mt][nt][0]), "+f"(acc[mt][nt][1]),
                          "+f"(acc[mt][nt][2]), "+f"(acc[mt][nt][3])
                        : "r"(a[mt][0]), "r"(a[mt][1]), "r"(a[mt][2]), "r"(a[mt][3]),
                          "r"(b[nt][0]), "r"(b[nt][1]));
                }
        }
        __syncthreads();
    }

    // epilogue: fp16 support store
    int g = lane >> 2, tg = lane & 3;
#pragma unroll
    for (int mt = 0; mt < 2; mt++) {
        int m = m0 + warp_m * 32 + mt * 16 + g;
#pragma unroll
        for (int nt = 0; nt < 8; nt++) {
            int n = n0 + warp_n * 64 + nt * 8 + tg * 2;
            __half2 lo2 = __floats2half2_rn(acc[mt][nt][0], acc[mt][nt][1]);
            __half2 hi2 = __floats2half2_rn(acc[mt][nt][2], acc[mt][nt][3]);
            *(__half2*)(g_support_h + (size_t)m * EMBED_DIM + n) = lo2;
            *(__half2*)(g_support_h + (size_t)(m + 8) * EMBED_DIM + n) = hi2;
        }
    }
}

// ---------------- fused SpMM (CSR, fp16 support) + bias + LayerNorm ----------------
__global__ __launch_bounds__(64) void spmm_ln_kernel(const float* __restrict__ bias,
                                                     const float* __restrict__ gamma,
                                                     const float* __restrict__ beta,
                                                     float* __restrict__ out) {
    int r = blockIdx.x;
    int t = threadIdx.x;
    __shared__ int2 s_edge[64];
    __shared__ float red[4];

    int beg = g_ptr[r];
    int end = g_ptr[r + 1];

    float acc[8];
#pragma unroll
    for (int q = 0; q < 8; q++) acc[q] = 0.f;

    for (int base = beg; base < end; base += 64) {
        int cnt = min(64, end - base);
        if (t < cnt) s_edge[t] = g_edge[base + t];
        __syncthreads();
#pragma unroll 4
        for (int i = 0; i < cnt; i++) {
            int2 e = s_edge[i];
            float v = __int_as_float(e.y);
            uint4 raw = *(const uint4*)(g_support_h + (size_t)e.x * EMBED_DIM + t * 8);
            float2 f0 = __half22float2(*reinterpret_cast<__half2*>(&raw.x));
            float2 f1 = __half22float2(*reinterpret_cast<__half2*>(&raw.y));
            float2 f2 = __half22float2(*reinterpret_cast<__half2*>(&raw.z));
            float2 f3 = __half22float2(*reinterpret_cast<__half2*>(&raw.w));
            acc[0] += v * f0.x; acc[1] += v * f0.y;
            acc[2] += v * f1.x; acc[3] += v * f1.y;
            acc[4] += v * f2.x; acc[5] += v * f2.y;
            acc[6] += v * f3.x; acc[7] += v * f3.y;
        }
        __syncthreads();
    }

    const float4* b4 = (const float4*)(bias + t * 8);
    float4 ba = b4[0], bb = b4[1];
    acc[0] += ba.x; acc[1] += ba.y; acc[2] += ba.z; acc[3] += ba.w;
    acc[4] += bb.x; acc[5] += bb.y; acc[6] += bb.z; acc[7] += bb.w;

    float s = 0.f, q = 0.f;
#pragma unroll
    for (int j = 0; j < 8; j++) { s += acc[j]; q += acc[j] * acc[j]; }
#pragma unroll
    for (int o = 16; o > 0; o >>= 1) {
        s += __shfl_down_sync(0xFFFFFFFFu, s, o);
        q += __shfl_down_sync(0xFFFFFFFFu, q, o);
    }
    int lane = t & 31, w = t >> 5;
    if (lane == 0) { red[w] = s; red[2 + w] = q; }
    __syncthreads();
    if (t == 0) {
        float S = red[0] + red[1];
        float Q = red[2] + red[3];
        float mu = S * (1.0f / EMBED_DIM);
        float var = Q * (1.0f / EMBED_DIM) - mu * mu;
        red[0] = mu;
        red[1] = rsqrtf(var + LN_EPS);
    }
    __syncthreads();
    float mu = red[0], rs = red[1];

    const float4* g4 = (const float4*)(gamma + t * 8);
    const float4* be4 = (const float4*)(beta + t * 8);
    float4 g0 = g4[0], g1 = g4[1], e0 = be4[0], e1 = be4[1];
    float4 o0, o1;
    o0.x = (acc[0] - mu) * rs * g0.x + e0.x;
    o0.y = (acc[1] - mu) * rs * g0.y + e0.y;
    o0.z = (acc[2] - mu) * rs * g0.z + e0.z;
    o0.w = (acc[3] - mu) * rs * g0.w + e0.w;
    o1.x = (acc[4] - mu) * rs * g1.x + e1.x;
    o1.y = (acc[5] - mu) * rs * g1.y + e1.y;
    o1.z = (acc[6] - mu) * rs * g1.z + e1.z;
    o1.w = (acc[7] - mu) * rs * g1.w + e1.w;
    float4* op = (float4*)(out + (size_t)r * EMBED_DIM + t * 8);
    op[0] = o0;
    op[1] = o1;
}

// ---------------- launch ----------------
extern "C" void kernel_launch(void* const* d_in, const int* in_sizes, int n_in,
                              void* d_out, int out_size) {
    const int*   uid   = (const int*)d_in[0];
    const int*   arow  = (const int*)d_in[1];
    const int*   acol  = (const int*)d_in[2];
    const float* avals = (const float*)d_in[3];
    const float* emb   = (const float*)d_in[4];
    const float* W     = (const float*)d_in[5];
    const float* bias  = (const float*)d_in[6];
    const float* gamma = (const float*)d_in[7];
    const float* beta  = (const float*)d_in[8];
    float* out = (float*)d_out;

    prep_all<<<13312, 256>>>(W, arow, uid, emb);
    scanA_kernel<<<32, 1024>>>();
    scanB_kernel<<<1, 1024>>>();
    gemm_scatter<<<5120, 256>>>(arow, acol, avals);
    spmm_ln_kernel<<<N_NODES, 64>>>(bias, gamma, beta, out);
}